// round 3
// baseline (speedup 1.0000x reference)
#include <cuda_runtime.h>
#include <cuda_bf16.h>
#include <cstdint>

// SequenceEmbedding: out[0][c][i][j] = one_hot(seq[i])[c]          for c in [0,4)
//                    out[0][c][i][j] = one_hot(seq[j])[c-4]        for c in [4,8)
// with one_hot(s) = base_table[s] (4-vector). Output (1, 8, 4096, 4096) fp32.
// Pure HBM-write-bound: 536.9 MB of stores, ~0 required reads.

#define SEQ_L   4096
#define NB      4
#define ROWS_PB 16          // rows per block
#define TPB     256         // threads per block

// Detect whether seq buffer is int64 or int32. Values are in [0,4), so for an
// int64 little-endian layout every odd 32-bit word is 0. For random int32 data
// the probability all 64 sampled odd words are 0 is 4^-64 (~1e-39).
__device__ __forceinline__ bool seq_is_int64(const int* s32) {
    bool is64 = true;
#pragma unroll
    for (int k = 0; k < 64; k++) {
        if (s32[2 * k + 1] != 0) is64 = false;
    }
    return is64;
}

__device__ __forceinline__ int seq_at(const void* seq, int i, bool is64) {
    if (is64) return (int)((const long long*)seq)[i];
    return ((const int*)seq)[i];
}

__global__ void __launch_bounds__(TPB)
SequenceEmbedding_30923764532139_kernel(const void* __restrict__ seq,
                                        const float* __restrict__ bt,
                                        float* __restrict__ out) {
    const int bx = blockIdx.x;
    const int c  = bx >> 8;              // 256 blocks per channel, 8 channels
    const int i0 = (bx & 255) * ROWS_PB; // first row handled by this block
    const int t  = threadIdx.x;

    const bool is64 = seq_is_int64((const int*)seq);

    float4* __restrict__ chan =
        (float4*)(out + (size_t)c * SEQ_L * SEQ_L);
    const int row_f4 = SEQ_L / 4;        // 1024 float4 per row

    if (c < NB) {
        // Row-splat channels: value constant along j, varies per row i.
#pragma unroll
        for (int r = 0; r < ROWS_PB; r++) {
            const int i = i0 + r;
            const float v = bt[seq_at(seq, i, is64) * NB + c];   // uniform, L1-hot
            const float4 vv = make_float4(v, v, v, v);
            float4* rowp = chan + (size_t)i * row_f4;
#pragma unroll
            for (int k = 0; k < 4; k++) {
                rowp[t + k * TPB] = vv;   // warp-contiguous 512B stores
            }
        }
    } else {
        // Column-pattern channels: every row of the channel is the same vector.
        // Materialize this thread's 16 pattern floats into registers once.
        const int cc = c - NB;
        float4 p[4];
#pragma unroll
        for (int k = 0; k < 4; k++) {
            const int j = 4 * (t + k * TPB);
            p[k].x = bt[seq_at(seq, j + 0, is64) * NB + cc];
            p[k].y = bt[seq_at(seq, j + 1, is64) * NB + cc];
            p[k].z = bt[seq_at(seq, j + 2, is64) * NB + cc];
            p[k].w = bt[seq_at(seq, j + 3, is64) * NB + cc];
        }
        // Replay across 16 rows: reads amortized 16x, all stores contiguous.
#pragma unroll
        for (int r = 0; r < ROWS_PB; r++) {
            float4* rowp = chan + (size_t)(i0 + r) * row_f4;
#pragma unroll
            for (int k = 0; k < 4; k++) {
                rowp[t + k * TPB] = p[k];
            }
        }
    }
}

extern "C" void kernel_launch(void* const* d_in, const int* in_sizes, int n_in,
                              void* d_out, int out_size) {
    const void*  seq = d_in[0];                 // 4096 ids (int32 or int64; auto-detected)
    const float* bt  = (const float*)d_in[1];   // 4x4 identity table, fp32
    float*       out = (float*)d_out;           // (1, 8, 4096, 4096) fp32

    const int total_rows = 8 * SEQ_L;                    // 32768
    const int grid = total_rows / ROWS_PB;               // 2048 blocks
    SequenceEmbedding_30923764532139_kernel<<<grid, TPB>>>(seq, bt, out);
}